// round 4
// baseline (speedup 1.0000x reference)
#include <cuda_runtime.h>
#include <cuda_bf16.h>

// SiLU(x) = x * sigmoid(x), elementwise, n = 134217728 fp32.
// Persistent grid-stride streaming kernel: one wave of 148*8 CTAs,
// each CTA walks tiles of 1024 float4s with 4 batched LDG.128 (MLP=4),
// non-temporal hints (zero reuse).

__device__ __forceinline__ float silu1(float x) {
    float s = 1.0f / (1.0f + __expf(-x));
    return x * s;
}

__device__ __forceinline__ float4 silu4(float4 v) {
    float4 r;
    r.x = silu1(v.x);
    r.y = silu1(v.y);
    r.z = silu1(v.z);
    r.w = silu1(v.w);
    return r;
}

// Tile = 1024 float4s. Thread t handles offsets t, t+256, t+512, t+768
// within each tile -> 4 independent in-flight LDG.128, fully coalesced.
__global__ void __launch_bounds__(256) silu_persist_kernel(
    const float4* __restrict__ in, float4* __restrict__ out,
    int n4, int ntiles)
{
    int t = threadIdx.x;
    for (int tile = blockIdx.x; tile < ntiles; tile += gridDim.x) {
        int base = tile * 1024 + t;
        if (base + 768 < n4) {
            float4 v0 = __ldcs(in + base);
            float4 v1 = __ldcs(in + base + 256);
            float4 v2 = __ldcs(in + base + 512);
            float4 v3 = __ldcs(in + base + 768);
            __stcs(out + base,       silu4(v0));
            __stcs(out + base + 256, silu4(v1));
            __stcs(out + base + 512, silu4(v2));
            __stcs(out + base + 768, silu4(v3));
        } else {
            #pragma unroll
            for (int k = 0; k < 4; k++) {
                int i = base + k * 256;
                if (i < n4) __stcs(out + i, silu4(__ldcs(in + i)));
            }
        }
    }
}

// Tail for n not divisible by 4 (not hit for this shape).
__global__ void silu_tail_kernel(const float* __restrict__ in,
                                 float* __restrict__ out, int start, int n)
{
    int i = start + blockIdx.x * blockDim.x + threadIdx.x;
    if (i < n) out[i] = silu1(in[i]);
}

extern "C" void kernel_launch(void* const* d_in, const int* in_sizes, int n_in,
                              void* d_out, int out_size)
{
    const float* x = (const float*)d_in[0];
    float* y = (float*)d_out;
    int n = in_sizes[0];

    int n4 = n / 4;
    if (n4 > 0) {
        int ntiles = (n4 + 1023) / 1024;
        int grid = 148 * 8;               // one full-occupancy wave on B300/GB300
        if (grid > ntiles) grid = ntiles; // tiny-input safety
        silu_persist_kernel<<<grid, 256>>>(
            (const float4*)x, (float4*)y, n4, ntiles);
    }
    int rem = n - n4 * 4;
    if (rem > 0) {
        silu_tail_kernel<<<1, 256>>>(x, y, n4 * 4, n);
    }
}

// round 5
// speedup vs baseline: 1.0837x; 1.0837x over previous
#include <cuda_runtime.h>
#include <cuda_bf16.h>

// SiLU(x) = x * sigmoid(x), elementwise, n = 134217728 fp32.
// HBM-bound stream at the read/write-turnaround ceiling.
// Fast path (n4 % 1024 == 0, true for this shape): no bounds checks,
// 4 front-batched LDG.128 per thread (MLP=4), non-temporal hints,
// one-shot grid of 32768 CTAs (hardware wave scheduling).

__device__ __forceinline__ float silu1(float x) {
    float s = 1.0f / (1.0f + __expf(-x));
    return x * s;
}

__device__ __forceinline__ float4 silu4(float4 v) {
    float4 r;
    r.x = silu1(v.x);
    r.y = silu1(v.y);
    r.z = silu1(v.z);
    r.w = silu1(v.w);
    return r;
}

// Full-tile kernel: every block owns exactly 1024 float4s, no guards.
__global__ void __launch_bounds__(256) silu_vec4x4_full_kernel(
    const float4* __restrict__ in, float4* __restrict__ out)
{
    unsigned base = blockIdx.x * 1024u + threadIdx.x;
    float4 v0 = __ldcs(in + base);
    float4 v1 = __ldcs(in + base + 256);
    float4 v2 = __ldcs(in + base + 512);
    float4 v3 = __ldcs(in + base + 768);
    __stcs(out + base,       silu4(v0));
    __stcs(out + base + 256, silu4(v1));
    __stcs(out + base + 512, silu4(v2));
    __stcs(out + base + 768, silu4(v3));
}

// Generic guarded kernel (fallback for shapes not divisible by tile).
__global__ void __launch_bounds__(256) silu_vec4x4_kernel(
    const float4* __restrict__ in, float4* __restrict__ out, int n4)
{
    int base = blockIdx.x * 1024 + threadIdx.x;
    #pragma unroll
    for (int k = 0; k < 4; k++) {
        int i = base + k * 256;
        if (i < n4) __stcs(out + i, silu4(__ldcs(in + i)));
    }
}

// Tail for n not divisible by 4 (not hit for this shape).
__global__ void silu_tail_kernel(const float* __restrict__ in,
                                 float* __restrict__ out, int start, int n)
{
    int i = start + blockIdx.x * blockDim.x + threadIdx.x;
    if (i < n) out[i] = silu1(in[i]);
}

extern "C" void kernel_launch(void* const* d_in, const int* in_sizes, int n_in,
                              void* d_out, int out_size)
{
    const float* x = (const float*)d_in[0];
    float* y = (float*)d_out;
    int n = in_sizes[0];

    int n4 = n / 4;
    if (n4 > 0) {
        if ((n4 & 1023) == 0) {
            // exact full tiles — no-guard fast path
            silu_vec4x4_full_kernel<<<n4 / 1024, 256>>>(
                (const float4*)x, (float4*)y);
        } else {
            silu_vec4x4_kernel<<<(n4 + 1023) / 1024, 256>>>(
                (const float4*)x, (float4*)y, n4);
        }
    }
    int rem = n - n4 * 4;
    if (rem > 0) {
        silu_tail_kernel<<<1, 256>>>(x, y, n4 * 4, n);
    }
}

// round 6
// speedup vs baseline: 1.0892x; 1.0051x over previous
#include <cuda_runtime.h>
#include <cuda_bf16.h>

// SiLU(x) = x * sigmoid(x), elementwise, n = 134217728 fp32.
// HBM-bound stream near the read/write-turnaround ceiling (~6.8 TB/s measured).
// 512-thread blocks, 4 front-batched LDG.128 per thread (MLP=4),
// tile = 2048 float4s, grid = 16384, non-temporal hints.

__device__ __forceinline__ float silu1(float x) {
    float s = 1.0f / (1.0f + __expf(-x));
    return x * s;
}

__device__ __forceinline__ float4 silu4(float4 v) {
    float4 r;
    r.x = silu1(v.x);
    r.y = silu1(v.y);
    r.z = silu1(v.z);
    r.w = silu1(v.w);
    return r;
}

// Full-tile kernel: every block owns exactly 2048 float4s, no guards.
__global__ void __launch_bounds__(512) silu_b512_full_kernel(
    const float4* __restrict__ in, float4* __restrict__ out)
{
    unsigned base = blockIdx.x * 2048u + threadIdx.x;
    float4 v0 = __ldcs(in + base);
    float4 v1 = __ldcs(in + base + 512);
    float4 v2 = __ldcs(in + base + 1024);
    float4 v3 = __ldcs(in + base + 1536);
    __stcs(out + base,        silu4(v0));
    __stcs(out + base + 512,  silu4(v1));
    __stcs(out + base + 1024, silu4(v2));
    __stcs(out + base + 1536, silu4(v3));
}

// Generic guarded kernel (fallback for shapes not divisible by tile).
__global__ void __launch_bounds__(256) silu_vec4x4_kernel(
    const float4* __restrict__ in, float4* __restrict__ out, int n4)
{
    int base = blockIdx.x * 1024 + threadIdx.x;
    #pragma unroll
    for (int k = 0; k < 4; k++) {
        int i = base + k * 256;
        if (i < n4) __stcs(out + i, silu4(__ldcs(in + i)));
    }
}

// Tail for n not divisible by 4 (not hit for this shape).
__global__ void silu_tail_kernel(const float* __restrict__ in,
                                 float* __restrict__ out, int start, int n)
{
    int i = start + blockIdx.x * blockDim.x + threadIdx.x;
    if (i < n) out[i] = silu1(in[i]);
}

extern "C" void kernel_launch(void* const* d_in, const int* in_sizes, int n_in,
                              void* d_out, int out_size)
{
    const float* x = (const float*)d_in[0];
    float* y = (float*)d_out;
    int n = in_sizes[0];

    int n4 = n / 4;
    if (n4 > 0) {
        if ((n4 & 2047) == 0) {
            // exact full tiles — no-guard fast path, 512-thread blocks
            silu_b512_full_kernel<<<n4 / 2048, 512>>>(
                (const float4*)x, (float4*)y);
        } else {
            silu_vec4x4_kernel<<<(n4 + 1023) / 1024, 256>>>(
                (const float4*)x, (float4*)y, n4);
        }
    }
    int rem = n - n4 * 4;
    if (rem > 0) {
        silu_tail_kernel<<<1, 256>>>(x, y, n4 * 4, n);
    }
}